// round 1
// baseline (speedup 1.0000x reference)
#include <cuda_runtime.h>
#include <cstdint>

// out[b,t,f] = relu( r2[t<16][f] + sum_c sign(x[b,t,c])*sign(w_sc[c,f]) )
//
// Derivation: conv2's input is ste_sign(relu(...)) == +1 everywhere (sign(0)=+1),
// so the conv1 branch is dead and conv2+bn2 collapse to a per-f constant table
// (two variants: t<16 sees the causal zero-pad on the dilated tap).
// The shortcut is an exact +-1 binary GEMM done with XOR+popcount.

#define EPSBN 1e-3f

__device__ uint4 g_wbits[128];   // per output f: word j bit l = (w_sc[32j+l, f] >= 0)
__device__ float g_r2[2][128];   // [0] = t>=16 table, [1] = t<16 table

__global__ void precompute_kernel(const float* __restrict__ w2,
                                  const float* __restrict__ w_sc,
                                  const float* __restrict__ beta2,
                                  const float* __restrict__ mean2,
                                  const float* __restrict__ var2) {
    int tid = threadIdx.x;      // 512 threads
    int f = tid & 127;
    int j = tid >> 7;

    // Pack shortcut weight sign bits: bit l of word j <=> channel c = 32j + l
    unsigned w = 0u;
#pragma unroll
    for (int l = 0; l < 32; ++l) {
        int c = 32 * j + l;
        if (w_sc[c * 128 + f] >= 0.f) w |= (1u << l);
    }
    reinterpret_cast<unsigned*>(&g_wbits[f])[j] = w;

    if (tid < 128) {
        int S01 = 0, S1 = 0;
        for (int c = 0; c < 128; ++c) {
            float a = w2[c * 128 + f];           // k=0 tap
            float b = w2[16384 + c * 128 + f];   // k=1 tap
            int sa = (a >= 0.f) ? 1 : -1;
            int sb = (b >= 0.f) ? 1 : -1;
            S01 += sa + sb;
            S1  += sb;
        }
        float inv = rsqrtf(var2[f] + EPSBN);
        g_r2[0][f] = fmaxf(((float)S01 - mean2[f]) * inv + beta2[f], 0.f);
        g_r2[1][f] = fmaxf(((float)S1  - mean2[f]) * inv + beta2[f], 0.f);
    }
}

__global__ void __launch_bounds__(256)
resblock_main_kernel(const float* __restrict__ x, float* __restrict__ out) {
    __shared__ uint4 s_w[128];
    __shared__ float s_r2[2][128];

    int tid = threadIdx.x;
    if (tid < 128) {
        s_w[tid]    = g_wbits[tid];
        s_r2[0][tid] = g_r2[0][tid];
        s_r2[1][tid] = g_r2[1][tid];
    }
    __syncthreads();

    int warp = tid >> 5;
    int lane = tid & 31;
    int row  = blockIdx.x * 8 + warp;       // row = b*8192 + t, 262144 rows total

    const float* xr = x + (size_t)row * 128;
    // Coalesced: each of the 4 loads is a contiguous 128B warp transaction
    float v0 = xr[lane];
    float v1 = xr[lane + 32];
    float v2 = xr[lane + 64];
    float v3 = xr[lane + 96];

    unsigned m0 = __ballot_sync(0xffffffffu, v0 >= 0.f);
    unsigned m1 = __ballot_sync(0xffffffffu, v1 >= 0.f);
    unsigned m2 = __ballot_sync(0xffffffffu, v2 >= 0.f);
    unsigned m3 = __ballot_sync(0xffffffffu, v3 >= 0.f);

    int t = row & 8191;
    const float* bias = (t < 16) ? s_r2[1] : s_r2[0];

    float* outr = out + (size_t)row * 128;
#pragma unroll
    for (int j = 0; j < 4; ++j) {
        int f = lane + 32 * j;
        uint4 wb = s_w[f];
        int pc = __popc(m0 ^ wb.x) + __popc(m1 ^ wb.y)
               + __popc(m2 ^ wb.z) + __popc(m3 ^ wb.w);
        float d = (float)(128 - 2 * pc);
        outr[f] = fmaxf(d + bias[f], 0.f);
    }
}

extern "C" void kernel_launch(void* const* d_in, const int* in_sizes, int n_in,
                              void* d_out, int out_size) {
    const float* x     = (const float*)d_in[0];
    // d_in[1] = w1   (dead: conv1 branch never affects the output)
    const float* w2    = (const float*)d_in[2];
    const float* w_sc  = (const float*)d_in[3];
    // d_in[4..6] = beta1/mean1/var1 (dead)
    const float* beta2 = (const float*)d_in[7];
    const float* mean2 = (const float*)d_in[8];
    const float* var2  = (const float*)d_in[9];
    float* out = (float*)d_out;

    precompute_kernel<<<1, 512>>>(w2, w_sc, beta2, mean2, var2);

    // 32*8192 = 262144 rows, 8 rows (1 per warp) per 256-thread block
    resblock_main_kernel<<<262144 / 8, 256>>>(x, out);
}

// round 3
// speedup vs baseline: 1.1215x; 1.1215x over previous
#include <cuda_runtime.h>
#include <cstdint>

// out[b,t,f] = relu( r2[t<16][f] + sum_c sign(x[b,t,c])*sign(w_sc[c,f]) )
//
// conv2's input is ste_sign(relu(...)) == +1 everywhere (sign(0)=+1), so the
// conv1 branch is dead and conv2+bn2 collapse to a per-f constant table (two
// variants: t<16 sees the causal zero-pad on the dilated tap). The shortcut is
// an exact +-1 binary GEMM via XOR+popcount.
//
// R3 (= R2 resubmit after infra failure): float4 I/O (1 LDG.128 + 1 STG.128
// per thread per row), weight bits packed in float4-ballot channel order
// (word k, bit l <-> channel 4l+k; popcount is permutation-invariant),
// weights/bias hoisted to registers across a 16-row per-warp loop (no in-loop
// LDS), full unroll of the row loop for high LDG MLP.

#define EPSBN 1e-3f
#define ROWS_PER_WARP 16

__device__ uint4 g_wbits[128];   // f -> packed sign bits, permuted channel order
__device__ float g_r2[2][128];   // [0]=t>=16 table, [1]=t<16 table

__global__ void precompute_kernel(const float* __restrict__ w2,
                                  const float* __restrict__ w_sc,
                                  const float* __restrict__ beta2,
                                  const float* __restrict__ mean2,
                                  const float* __restrict__ var2) {
    __shared__ int sh01[4][128];
    __shared__ int sh1[4][128];

    int tid = threadIdx.x;      // 512 threads
    int f = tid & 127;
    int k = tid >> 7;           // word index 0..3

    // Permuted packing to match float4-load ballots in the main kernel:
    // word k, bit l  <->  channel c = 4*l + k
    unsigned w = 0u;
#pragma unroll
    for (int l = 0; l < 32; ++l) {
        int c = 4 * l + k;
        if (w_sc[c * 128 + f] >= 0.f) w |= (1u << l);
    }
    reinterpret_cast<unsigned*>(&g_wbits[f])[k] = w;

    // Parallel reduction of the conv2 sign-sums: group k handles c in [32k,32k+32)
    int S01 = 0, S1 = 0;
#pragma unroll 4
    for (int cc = 0; cc < 32; ++cc) {
        int c = 32 * k + cc;
        float a = w2[c * 128 + f];           // k=0 tap
        float b = w2[16384 + c * 128 + f];   // k=1 tap
        int sa = (a >= 0.f) ? 1 : -1;
        int sb = (b >= 0.f) ? 1 : -1;
        S01 += sa + sb;
        S1  += sb;
    }
    sh01[k][f] = S01;
    sh1[k][f]  = S1;
    __syncthreads();

    if (tid < 128) {
        int t01 = sh01[0][f] + sh01[1][f] + sh01[2][f] + sh01[3][f];
        int t1  = sh1[0][f]  + sh1[1][f]  + sh1[2][f]  + sh1[3][f];
        float inv = rsqrtf(var2[f] + EPSBN);
        g_r2[0][f] = fmaxf(((float)t01 - mean2[f]) * inv + beta2[f], 0.f);
        g_r2[1][f] = fmaxf(((float)t1  - mean2[f]) * inv + beta2[f], 0.f);
    }
}

__global__ void __launch_bounds__(256)
resblock_main_kernel(const float* __restrict__ x, float* __restrict__ out) {
    __shared__ uint4 s_w[128];
    __shared__ float s_r2[2][128];

    int tid = threadIdx.x;
    if (tid < 128) {
        s_w[tid]     = g_wbits[tid];
        s_r2[0][tid] = g_r2[0][tid];
        s_r2[1][tid] = g_r2[1][tid];
    }
    __syncthreads();

    int lane = tid & 31;
    int warp = tid >> 5;

    // Hoist this thread's 4 output columns' weights + both bias variants
    uint4 wb[4];
    float bH[4], bL[4];
#pragma unroll
    for (int i = 0; i < 4; ++i) {
        int f = 4 * lane + i;
        wb[i] = s_w[f];
        bH[i] = s_r2[0][f];
        bL[i] = s_r2[1][f];
    }

    const float4* __restrict__ x4 = (const float4*)x;
    float4* __restrict__ o4 = (float4*)out;

    size_t row0 = ((size_t)blockIdx.x * 8 + warp) * ROWS_PER_WARP;

#pragma unroll
    for (int r = 0; r < ROWS_PER_WARP; ++r) {
        size_t row = row0 + r;
        // One 128-bit load: thread lane holds channels 4*lane .. 4*lane+3
        float4 v = x4[row * 32 + lane];

        unsigned m0 = __ballot_sync(0xffffffffu, v.x >= 0.f);
        unsigned m1 = __ballot_sync(0xffffffffu, v.y >= 0.f);
        unsigned m2 = __ballot_sync(0xffffffffu, v.z >= 0.f);
        unsigned m3 = __ballot_sync(0xffffffffu, v.w >= 0.f);

        bool early = (row & 8191) < 16;

        float o[4];
#pragma unroll
        for (int i = 0; i < 4; ++i) {
            int pc = __popc(m0 ^ wb[i].x) + __popc(m1 ^ wb[i].y)
                   + __popc(m2 ^ wb[i].z) + __popc(m3 ^ wb[i].w);
            float d = (float)(128 - 2 * pc);
            float bias = early ? bL[i] : bH[i];
            o[i] = fmaxf(d + bias, 0.f);
        }

        o4[row * 32 + lane] = make_float4(o[0], o[1], o[2], o[3]);
    }
}

extern "C" void kernel_launch(void* const* d_in, const int* in_sizes, int n_in,
                              void* d_out, int out_size) {
    const float* x     = (const float*)d_in[0];
    // d_in[1] = w1 (dead), d_in[4..6] = bn1 params (dead)
    const float* w2    = (const float*)d_in[2];
    const float* w_sc  = (const float*)d_in[3];
    const float* beta2 = (const float*)d_in[7];
    const float* mean2 = (const float*)d_in[8];
    const float* var2  = (const float*)d_in[9];
    float* out = (float*)d_out;

    precompute_kernel<<<1, 512>>>(w2, w_sc, beta2, mean2, var2);

    // 262144 rows total, 8 warps/block * 16 rows/warp = 128 rows/block
    resblock_main_kernel<<<262144 / (8 * ROWS_PER_WARP), 256>>>(x, out);
}

// round 5
// speedup vs baseline: 1.2232x; 1.0906x over previous
#include <cuda_runtime.h>
#include <cstdint>

// out[b,t,f] = relu( r2[t<16][f] + sum_c sign(x[b,t,c])*sign(w_sc[c,f]) )
//
// conv2's input is ste_sign(relu(...)) == +1 everywhere (sign(0)=+1), so the
// conv1 branch is dead and conv2+bn2 collapse to a per-f constant table (two
// variants: t<16 sees the causal zero-pad on the dilated tap). The shortcut is
// an exact +-1 binary GEMM via XOR+popcount.
//
// R5 (= R4 resubmit after infra failure): cp.async double-buffered smem
// pipeline (in-flight loads not register-resident -> high MLP at low regs),
// biases folded to bias+128 with FFMA(-2,pc), rare t<16 bias via predicated
// reload, precompute parallelized across 12 blocks + tiny finalize.

#define EPSBN 1e-3f
#define TILE_ROWS 32
#define NTILES 4
#define ROWS_PER_BLOCK (TILE_ROWS * NTILES)   // 128 rows/block
#define TOTAL_ROWS (32 * 8192)                // 262144

__device__ uint4 g_wbits[128];   // f -> packed sign bits (word k bit l <-> channel 4l+k)
__device__ float g_r2[2][128];   // [0]=t>=16 bias table, [1]=t<16 table
__device__ int   g_part[8][2][128];

// ---------------- precompute, stage 1: 12 blocks x 128 threads ----------------
__global__ void precompute1(const float* __restrict__ w2,
                            const float* __restrict__ w_sc) {
    int f = threadIdx.x;
    int b = blockIdx.x;
    if (b < 4) {
        // pack word k of the shortcut-weight sign bits (float4-ballot order)
        int k = b;
        unsigned w = 0u;
#pragma unroll
        for (int l = 0; l < 32; ++l) {
            int c = 4 * l + k;
            if (w_sc[c * 128 + f] >= 0.f) w |= (1u << l);
        }
        reinterpret_cast<unsigned*>(&g_wbits[f])[k] = w;
    } else {
        // partial conv2 sign-sums over a 16-channel slice
        int j = b - 4;
        int S01 = 0, S1 = 0;
#pragma unroll
        for (int cc = 0; cc < 16; ++cc) {
            int c = 16 * j + cc;
            float a  = w2[c * 128 + f];           // tap k=0
            float bb = w2[16384 + c * 128 + f];   // tap k=1
            S01 += ((a >= 0.f) ? 1 : -1) + ((bb >= 0.f) ? 1 : -1);
            S1  += ((bb >= 0.f) ? 1 : -1);
        }
        g_part[j][0][f] = S01;
        g_part[j][1][f] = S1;
    }
}

// ---------------- precompute, stage 2: finalize bias tables ----------------
__global__ void precompute2(const float* __restrict__ beta2,
                            const float* __restrict__ mean2,
                            const float* __restrict__ var2) {
    int f = threadIdx.x;
    int t01 = 0, t1 = 0;
#pragma unroll
    for (int j = 0; j < 8; ++j) { t01 += g_part[j][0][f]; t1 += g_part[j][1][f]; }
    float inv = rsqrtf(var2[f] + EPSBN);
    g_r2[0][f] = fmaxf(((float)t01 - mean2[f]) * inv + beta2[f], 0.f);
    g_r2[1][f] = fmaxf(((float)t1  - mean2[f]) * inv + beta2[f], 0.f);
}

// ---------------- main kernel ----------------
__device__ __forceinline__ void cp_async16(uint32_t smem_addr, const void* gptr) {
    asm volatile("cp.async.cg.shared.global [%0], [%1], 16;\n"
                 :: "r"(smem_addr), "l"(gptr));
}
__device__ __forceinline__ void cp_commit() {
    asm volatile("cp.async.commit_group;\n" ::: "memory");
}
template <int N>
__device__ __forceinline__ void cp_wait() {
    asm volatile("cp.async.wait_group %0;\n" :: "n"(N) : "memory");
}

__global__ void __launch_bounds__(256, 6)
resblock_main(const float* __restrict__ x, float* __restrict__ out) {
    __shared__ float4 s_x[2][TILE_ROWS * 32];   // 2 x 16 KB

    int tid  = threadIdx.x;
    int lane = tid & 31;
    int warp = tid >> 5;

    // Hoist this thread's 4 output columns: weights + folded bias (bias + 128)
    uint4 wb0 = g_wbits[4 * lane + 0];
    uint4 wb1 = g_wbits[4 * lane + 1];
    uint4 wb2 = g_wbits[4 * lane + 2];
    uint4 wb3 = g_wbits[4 * lane + 3];
    float bP0 = g_r2[0][4 * lane + 0] + 128.f;
    float bP1 = g_r2[0][4 * lane + 1] + 128.f;
    float bP2 = g_r2[0][4 * lane + 2] + 128.f;
    float bP3 = g_r2[0][4 * lane + 3] + 128.f;

    size_t row_base = (size_t)blockIdx.x * ROWS_PER_BLOCK;
    const float4* __restrict__ gx = (const float4*)x + row_base * 32;
    float4* __restrict__ o4 = (float4*)out;

    uint32_t sbase = (uint32_t)__cvta_generic_to_shared(&s_x[0][0]);

    // issue tile 0
#pragma unroll
    for (int j = 0; j < 4; ++j) {
        int idx = tid + j * 256;                  // 1024 float4 = 32 rows
        cp_async16(sbase + idx * 16, gx + idx);
    }
    cp_commit();

#pragma unroll
    for (int t = 0; t < NTILES; ++t) {
        if (t + 1 < NTILES) {
            uint32_t dst = sbase + ((t + 1) & 1) * (TILE_ROWS * 32 * 16);
            const float4* src = gx + (size_t)(t + 1) * TILE_ROWS * 32;
#pragma unroll
            for (int j = 0; j < 4; ++j) {
                int idx = tid + j * 256;
                cp_async16(dst + idx * 16, src + idx);
            }
            cp_commit();
            cp_wait<1>();
        } else {
            cp_wait<0>();
        }
        __syncthreads();

        const float4* buf = s_x[t & 1];
#pragma unroll
        for (int rr = 0; rr < TILE_ROWS / 8; ++rr) {   // 4 rows per warp per tile
            int rloc = warp * (TILE_ROWS / 8) + rr;
            float4 v = buf[rloc * 32 + lane];

            unsigned m0 = __ballot_sync(0xffffffffu, v.x >= 0.f);
            unsigned m1 = __ballot_sync(0xffffffffu, v.y >= 0.f);
            unsigned m2 = __ballot_sync(0xffffffffu, v.z >= 0.f);
            unsigned m3 = __ballot_sync(0xffffffffu, v.w >= 0.f);

            size_t row = row_base + (size_t)t * TILE_ROWS + rloc;

            float p0 = bP0, p1 = bP1, p2 = bP2, p3 = bP3;
            if ((row & 8191) < 16) {               // 512 of 262144 rows
                p0 = g_r2[1][4 * lane + 0] + 128.f;
                p1 = g_r2[1][4 * lane + 1] + 128.f;
                p2 = g_r2[1][4 * lane + 2] + 128.f;
                p3 = g_r2[1][4 * lane + 3] + 128.f;
            }

            int c0 = __popc(m0 ^ wb0.x) + __popc(m1 ^ wb0.y) + __popc(m2 ^ wb0.z) + __popc(m3 ^ wb0.w);
            int c1 = __popc(m0 ^ wb1.x) + __popc(m1 ^ wb1.y) + __popc(m2 ^ wb1.z) + __popc(m3 ^ wb1.w);
            int c2 = __popc(m0 ^ wb2.x) + __popc(m1 ^ wb2.y) + __popc(m2 ^ wb2.z) + __popc(m3 ^ wb2.w);
            int c3 = __popc(m0 ^ wb3.x) + __popc(m1 ^ wb3.y) + __popc(m2 ^ wb3.z) + __popc(m3 ^ wb3.w);

            float4 o;
            o.x = fmaxf(fmaf(-2.f, (float)c0, p0), 0.f);
            o.y = fmaxf(fmaf(-2.f, (float)c1, p1), 0.f);
            o.z = fmaxf(fmaf(-2.f, (float)c2, p2), 0.f);
            o.w = fmaxf(fmaf(-2.f, (float)c3, p3), 0.f);
            o4[row * 32 + lane] = o;
        }
        __syncthreads();
    }
}

extern "C" void kernel_launch(void* const* d_in, const int* in_sizes, int n_in,
                              void* d_out, int out_size) {
    const float* x     = (const float*)d_in[0];
    // d_in[1] = w1 (dead), d_in[4..6] = bn1 params (dead)
    const float* w2    = (const float*)d_in[2];
    const float* w_sc  = (const float*)d_in[3];
    const float* beta2 = (const float*)d_in[7];
    const float* mean2 = (const float*)d_in[8];
    const float* var2  = (const float*)d_in[9];
    float* out = (float*)d_out;

    precompute1<<<12, 128>>>(w2, w_sc);
    precompute2<<<1, 128>>>(beta2, mean2, var2);
    resblock_main<<<TOTAL_ROWS / ROWS_PER_BLOCK, 256>>>(x, out);
}